// round 8
// baseline (speedup 1.0000x reference)
#include <cuda_runtime.h>
#include <cstdint>
#include <cstddef>

// ---------------------------------------------------------------------------
// AudioMamba forward on GB300 — R8: fusion round.
//  - LN fused into in_proj (stats precomputed)
//  - gate fused into out_proj A-load
//  - residual combine computes next-layer LN stats
//  - head LN+pool fused
// ---------------------------------------------------------------------------

constexpr int NS = 16;
constexpr int XDW = 64;

// ---- scratch --------------------------------------------------------------
constexpr size_t OFF_H    = 0;
constexpr size_t OFF_XZ   = OFF_H    + 1024 * 512;
constexpr size_t OFF_U0   = OFF_XZ   + 1024 * 2048;
constexpr size_t OFF_XD0  = OFF_U0   + 2 * 1024 * 1024;
constexpr size_t OFF_Y0   = OFF_XD0  + 2 * 1024 * XDW;
constexpr size_t OFF_IM   = OFF_Y0   + 2 * 1024 * 1024;
constexpr size_t OFF_XPP  = OFF_IM   + 1024 * 256;
constexpr size_t OFF_OPP  = OFF_XPP  + 16 * 1024 * 64;   // 4 x 1024 x 512
constexpr size_t OFF_ST   = OFF_OPP  + 4 * 1024 * 512;   // stats: 1024 x {mean,rstd}
constexpr size_t OFF_FEAT = OFF_ST   + 2 * 1024;
constexpr size_t OFF_C    = OFF_FEAT + 4 * 512;
constexpr size_t OFF_F1   = OFF_C    + 4 * 512;
constexpr size_t SCRATCH_FLOATS = OFF_F1 + 4 * 512;

__device__ __align__(16) float g_scratch[SCRATCH_FLOATS];

// ---------------------------------------------------------------------------
// tf32 helpers
// ---------------------------------------------------------------------------
__device__ __forceinline__ float f2tf32(float f) {
    uint32_t u;
    asm("cvt.rna.tf32.f32 %0, %1;" : "=r"(u) : "f"(f));
    return __uint_as_float(u);
}
__device__ __forceinline__ float4 cvt4(float4 v) {
    return make_float4(f2tf32(v.x), f2tf32(v.y), f2tf32(v.z), f2tf32(v.w));
}
__device__ __forceinline__ float silu(float z) {
    return z / (1.f + __expf(-z));
}

__device__ __forceinline__ void mma_tf32(float& c0, float& c1, float& c2, float& c3,
                                         uint32_t a0, uint32_t a1, uint32_t a2, uint32_t a3,
                                         uint32_t b0, uint32_t b1)
{
    asm volatile(
        "mma.sync.aligned.m16n8k8.row.col.f32.tf32.tf32.f32 "
        "{%0,%1,%2,%3}, {%4,%5,%6,%7}, {%8,%9}, {%0,%1,%2,%3};\n"
        : "+f"(c0), "+f"(c1), "+f"(c2), "+f"(c3)
        : "r"(a0), "r"(a1), "r"(a2), "r"(a3), "r"(b0), "r"(b1));
}

// ===========================================================================
// WIDE compute: shared inner loop over staged smem (128x128 tile, BK=16).
// Warp tile 32x64; wy=warp>>1 rows, wx=warp&1 cols.
// ===========================================================================
struct WideSmem {
    float As[2][128][20];
    float Bs[2][128][20];
};

__device__ __forceinline__ void wide_compute(const WideSmem& S, int cur,
                                             int wy, int wx, int g, int t,
                                             float (&acc)[2][8][4])
{
#pragma unroll
    for (int k8 = 0; k8 < 16; k8 += 8) {
        uint32_t a[2][4];
#pragma unroll
        for (int mf = 0; mf < 2; mf++) {
            const int ar = wy * 32 + mf * 16 + g;
            a[mf][0] = __float_as_uint(S.As[cur][ar][k8 + t]);
            a[mf][1] = __float_as_uint(S.As[cur][ar + 8][k8 + t]);
            a[mf][2] = __float_as_uint(S.As[cur][ar][k8 + t + 4]);
            a[mf][3] = __float_as_uint(S.As[cur][ar + 8][k8 + t + 4]);
        }
#pragma unroll
        for (int nt = 0; nt < 8; nt++) {
            const int bn = wx * 64 + nt * 8 + g;
            uint32_t b0 = __float_as_uint(S.Bs[cur][bn][k8 + t]);
            uint32_t b1 = __float_as_uint(S.Bs[cur][bn][k8 + t + 4]);
#pragma unroll
            for (int mf = 0; mf < 2; mf++)
                mma_tf32(acc[mf][nt][0], acc[mf][nt][1], acc[mf][nt][2], acc[mf][nt][3],
                         a[mf][0], a[mf][1], a[mf][2], a[mf][3], b0, b1);
        }
    }
}

#define WIDE_PROLOGUE                                             \
    const int tid  = threadIdx.x;                                 \
    const int warp = tid >> 5, lane = tid & 31;                   \
    const int wy = warp >> 1, wx = warp & 1;                      \
    const int g = lane >> 2, t = lane & 3;                        \
    const int row = tid >> 1, col = (tid & 1) * 8;                \
    float acc[2][8][4];                                           \
    _Pragma("unroll")                                             \
    for (int i = 0; i < 2; i++)                                   \
        _Pragma("unroll")                                         \
        for (int j = 0; j < 8; j++)                               \
            _Pragma("unroll")                                     \
            for (int q = 0; q < 4; q++) acc[i][j][q] = 0.f;       \
    (void)warp; (void)lane;

#define WIDE_EPILOGUE(Cptr, ldc, rowBase, colBase)                \
    _Pragma("unroll")                                             \
    for (int mf = 0; mf < 2; mf++) {                              \
        const int r0 = (rowBase) + wy * 32 + mf * 16 + g;         \
        _Pragma("unroll")                                         \
        for (int nt = 0; nt < 8; nt++) {                          \
            int cb = (colBase) + wx * 64 + nt * 8 + 2 * t;        \
            *reinterpret_cast<float2*>(&(Cptr)[(size_t)r0 * (ldc) + cb])       = make_float2(acc[mf][nt][0], acc[mf][nt][1]); \
            *reinterpret_cast<float2*>(&(Cptr)[(size_t)(r0 + 8) * (ldc) + cb]) = make_float2(acc[mf][nt][2], acc[mf][nt][3]); \
        }                                                         \
    }

// ---------------------------------------------------------------------------
// in_proj with fused LayerNorm on A: a = (h-mean)*rstd*gw + gb.
// grid (N/128, M/128). K = 512.
// ---------------------------------------------------------------------------
__global__ void __launch_bounds__(256)
gemm32_inproj(const float* __restrict__ H,
              const float* __restrict__ stats,   // [1024][2] mean,rstd
              const float* __restrict__ gw, const float* __restrict__ gb,
              const float* __restrict__ W,       // 2048 x 512
              float* __restrict__ C)             // 1024 x 2048
{
    __shared__ WideSmem S;
    const int rowBase = blockIdx.y * 128;
    const int colBase = blockIdx.x * 128;
    WIDE_PROLOGUE

    const float* Ab = H + (size_t)(rowBase + row) * 512;
    const float* Wb = W + (size_t)(colBase + row) * 512;
    const float  mu = stats[(rowBase + row) * 2];
    const float  rs = stats[(rowBase + row) * 2 + 1];

    auto ldA = [&](int k) -> float4 {
        float4 h4 = *reinterpret_cast<const float4*>(Ab + k);
        float4 w4 = *reinterpret_cast<const float4*>(gw + k);
        float4 b4 = *reinterpret_cast<const float4*>(gb + k);
        return make_float4(fmaf((h4.x - mu) * rs, w4.x, b4.x),
                           fmaf((h4.y - mu) * rs, w4.y, b4.y),
                           fmaf((h4.z - mu) * rs, w4.z, b4.z),
                           fmaf((h4.w - mu) * rs, w4.w, b4.w));
    };

    {
        *reinterpret_cast<float4*>(&S.As[0][row][col])     = cvt4(ldA(col));
        *reinterpret_cast<float4*>(&S.As[0][row][col + 4]) = cvt4(ldA(col + 4));
        *reinterpret_cast<float4*>(&S.Bs[0][row][col])     = cvt4(*reinterpret_cast<const float4*>(Wb + col));
        *reinterpret_cast<float4*>(&S.Bs[0][row][col + 4]) = cvt4(*reinterpret_cast<const float4*>(Wb + col + 4));
    }
    __syncthreads();

    const int niter = 512 >> 4;
    for (int it = 0; it < niter; it++) {
        const int cur = it & 1;
        float4 pa0, pa1, pb0, pb1;
        const bool more = (it + 1 < niter);
        if (more) {
            int k0 = (it + 1) << 4;
            pa0 = ldA(k0 + col);
            pa1 = ldA(k0 + col + 4);
            pb0 = *reinterpret_cast<const float4*>(Wb + k0 + col);
            pb1 = *reinterpret_cast<const float4*>(Wb + k0 + col + 4);
        }
        wide_compute(S, cur, wy, wx, g, t, acc);
        if (more) {
            const int nxt = cur ^ 1;
            *reinterpret_cast<float4*>(&S.As[nxt][row][col])     = cvt4(pa0);
            *reinterpret_cast<float4*>(&S.As[nxt][row][col + 4]) = cvt4(pa1);
            *reinterpret_cast<float4*>(&S.Bs[nxt][row][col])     = cvt4(pb0);
            *reinterpret_cast<float4*>(&S.Bs[nxt][row][col + 4]) = cvt4(pb1);
            __syncthreads();
        }
    }
    WIDE_EPILOGUE(C, 2048, rowBase, colBase)
}

// ---------------------------------------------------------------------------
// out_proj with fused gate on A: a = (y0[m] + y1[flip(m)]) * silu(z[m]).
// split-K(4): grid (4 n, 8 m, 4 kc). K-chunk 256.
// ---------------------------------------------------------------------------
__global__ void __launch_bounds__(256)
gemm32_op_gate(const float* __restrict__ ybase,   // [2][1024][1024]
               const float* __restrict__ xz,      // [1024][2048], z at +1024
               const float* __restrict__ Wop,     // 512 x 1024
               float* __restrict__ partial)       // [4][1024][512]
{
    __shared__ WideSmem S;
    const int kc = blockIdx.z;
    const int rowBase = blockIdx.y * 128;
    const int colBase = blockIdx.x * 128;
    WIDE_PROLOGUE

    const int m = rowBase + row;
    const int mflip = (m & ~255) + 255 - (m & 255);
    const float* y0r = ybase + (size_t)m * 1024 + kc * 256;
    const float* y1r = ybase + 1024 * 1024 + (size_t)mflip * 1024 + kc * 256;
    const float* zr  = xz + (size_t)m * 2048 + 1024 + kc * 256;
    const float* Wb  = Wop + (size_t)(colBase + row) * 1024 + kc * 256;

    auto ldA = [&](int k) -> float4 {
        float4 a = *reinterpret_cast<const float4*>(y0r + k);
        float4 b = *reinterpret_cast<const float4*>(y1r + k);
        float4 z = *reinterpret_cast<const float4*>(zr + k);
        return make_float4((a.x + b.x) * silu(z.x), (a.y + b.y) * silu(z.y),
                           (a.z + b.z) * silu(z.z), (a.w + b.w) * silu(z.w));
    };

    {
        *reinterpret_cast<float4*>(&S.As[0][row][col])     = cvt4(ldA(col));
        *reinterpret_cast<float4*>(&S.As[0][row][col + 4]) = cvt4(ldA(col + 4));
        *reinterpret_cast<float4*>(&S.Bs[0][row][col])     = cvt4(*reinterpret_cast<const float4*>(Wb + col));
        *reinterpret_cast<float4*>(&S.Bs[0][row][col + 4]) = cvt4(*reinterpret_cast<const float4*>(Wb + col + 4));
    }
    __syncthreads();

    const int niter = 256 >> 4;
    for (int it = 0; it < niter; it++) {
        const int cur = it & 1;
        float4 pa0, pa1, pb0, pb1;
        const bool more = (it + 1 < niter);
        if (more) {
            int k0 = (it + 1) << 4;
            pa0 = ldA(k0 + col);
            pa1 = ldA(k0 + col + 4);
            pb0 = *reinterpret_cast<const float4*>(Wb + k0 + col);
            pb1 = *reinterpret_cast<const float4*>(Wb + k0 + col + 4);
        }
        wide_compute(S, cur, wy, wx, g, t, acc);
        if (more) {
            const int nxt = cur ^ 1;
            *reinterpret_cast<float4*>(&S.As[nxt][row][col])     = cvt4(pa0);
            *reinterpret_cast<float4*>(&S.As[nxt][row][col + 4]) = cvt4(pa1);
            *reinterpret_cast<float4*>(&S.Bs[nxt][row][col])     = cvt4(pb0);
            *reinterpret_cast<float4*>(&S.Bs[nxt][row][col + 4]) = cvt4(pb1);
            __syncthreads();
        }
    }
    float* out = partial + (size_t)kc * (1024 * 512);
    WIDE_EPILOGUE(out, 512, rowBase, colBase)
}

// ---------------------------------------------------------------------------
// Residual combine + next-layer LN stats. One warp per row (512 wide).
// grid 128 x 256 threads (8 rows/block).
// ---------------------------------------------------------------------------
__global__ void op_combine_stats(const float* __restrict__ partial,
                                 float* __restrict__ h, float* __restrict__ stats)
{
    int rowid = (blockIdx.x * 256 + threadIdx.x) >> 5;
    int lane  = threadIdx.x & 31;
    float* hr = h + (size_t)rowid * 512;
    const float* p = partial + (size_t)rowid * 512;
    float s = 0.f, s2 = 0.f;
#pragma unroll
    for (int i = 0; i < 16; i++) {
        int c = lane + i * 32;
        float v = hr[c] + p[c] + p[c + 1024 * 512] + p[c + 2 * 1024 * 512] + p[c + 3 * 1024 * 512];
        hr[c] = v;
        s += v; s2 += v * v;
    }
#pragma unroll
    for (int o = 16; o; o >>= 1) {
        s  += __shfl_xor_sync(0xffffffffu, s, o);
        s2 += __shfl_xor_sync(0xffffffffu, s2, o);
    }
    if (lane == 0) {
        float m = s * (1.f / 512.f);
        float var = s2 * (1.f / 512.f) - m * m;
        stats[rowid * 2]     = m;
        stats[rowid * 2 + 1] = rsqrtf(var + 1e-5f);
    }
}

// Row stats only (after patch embed). One warp per row.
__global__ void stats_kernel(const float* __restrict__ h, float* __restrict__ stats)
{
    int rowid = (blockIdx.x * 256 + threadIdx.x) >> 5;
    int lane  = threadIdx.x & 31;
    const float* hr = h + (size_t)rowid * 512;
    float s = 0.f, s2 = 0.f;
#pragma unroll
    for (int i = 0; i < 16; i++) {
        float v = hr[lane + i * 32];
        s += v; s2 += v * v;
    }
#pragma unroll
    for (int o = 16; o; o >>= 1) {
        s  += __shfl_xor_sync(0xffffffffu, s, o);
        s2 += __shfl_xor_sync(0xffffffffu, s2, o);
    }
    if (lane == 0) {
        float m = s * (1.f / 512.f);
        float var = s2 * (1.f / 512.f) - m * m;
        stats[rowid * 2]     = m;
        stats[rowid * 2 + 1] = rsqrtf(var + 1e-5f);
    }
}

// ===========================================================================
// 64-wide core (128x64 tile) — patch embed and x_proj.
// ===========================================================================
__device__ __forceinline__ void mma_core_db(const float* __restrict__ Ab, int lda,
                                            const float* __restrict__ Wb, int ldw,
                                            int kend, float (&acc)[2][4][4])
{
    __shared__ __align__(16) float As[2][128][20];
    __shared__ __align__(16) float Bs[2][64][20];

    const int tid  = threadIdx.x;
    const int warp = tid >> 5, lane = tid & 31;
    const int wy = warp >> 1, wx = warp & 1;
    const int g = lane >> 2, t = lane & 3;

    const int arow = tid >> 1, acol = (tid & 1) * 8;
    const int brow = tid >> 2, bcol = (tid & 3) * 4;

    {
        float4 va0 = *reinterpret_cast<const float4*>(Ab + (size_t)arow * lda + acol);
        float4 va1 = *reinterpret_cast<const float4*>(Ab + (size_t)arow * lda + acol + 4);
        float4 vb  = *reinterpret_cast<const float4*>(Wb + (size_t)brow * ldw + bcol);
        *reinterpret_cast<float4*>(&As[0][arow][acol])     = cvt4(va0);
        *reinterpret_cast<float4*>(&As[0][arow][acol + 4]) = cvt4(va1);
        *reinterpret_cast<float4*>(&Bs[0][brow][bcol])     = cvt4(vb);
    }
    __syncthreads();

    const int niter = kend >> 4;
    for (int it = 0; it < niter; it++) {
        const int cur = it & 1;
        float4 pa0, pa1, pb;
        const bool more = (it + 1 < niter);
        if (more) {
            int k0 = (it + 1) << 4;
            pa0 = *reinterpret_cast<const float4*>(Ab + (size_t)arow * lda + k0 + acol);
            pa1 = *reinterpret_cast<const float4*>(Ab + (size_t)arow * lda + k0 + acol + 4);
            pb  = *reinterpret_cast<const float4*>(Wb + (size_t)brow * ldw + k0 + bcol);
        }

#pragma unroll
        for (int k8 = 0; k8 < 16; k8 += 8) {
            uint32_t a[2][4], b[4][2];
#pragma unroll
            for (int mf = 0; mf < 2; mf++) {
                const int ar = wy * 32 + mf * 16 + g;
                a[mf][0] = __float_as_uint(As[cur][ar][k8 + t]);
                a[mf][1] = __float_as_uint(As[cur][ar + 8][k8 + t]);
                a[mf][2] = __float_as_uint(As[cur][ar][k8 + t + 4]);
                a[mf][3] = __float_as_uint(As[cur][ar + 8][k8 + t + 4]);
            }
#pragma unroll
            for (int nt = 0; nt < 4; nt++) {
                const int bn = wx * 32 + nt * 8 + g;
                b[nt][0] = __float_as_uint(Bs[cur][bn][k8 + t]);
                b[nt][1] = __float_as_uint(Bs[cur][bn][k8 + t + 4]);
            }
#pragma unroll
            for (int mf = 0; mf < 2; mf++)
#pragma unroll
                for (int nt = 0; nt < 4; nt++)
                    mma_tf32(acc[mf][nt][0], acc[mf][nt][1], acc[mf][nt][2], acc[mf][nt][3],
                             a[mf][0], a[mf][1], a[mf][2], a[mf][3],
                             b[nt][0], b[nt][1]);
        }

        if (more) {
            const int nxt = cur ^ 1;
            *reinterpret_cast<float4*>(&As[nxt][arow][acol])     = cvt4(pa0);
            *reinterpret_cast<float4*>(&As[nxt][arow][acol + 4]) = cvt4(pa1);
            *reinterpret_cast<float4*>(&Bs[nxt][brow][bcol])     = cvt4(pb);
            __syncthreads();
        }
    }
}

#define MMA_PROLOGUE                                              \
    const int warp = threadIdx.x >> 5, lane = threadIdx.x & 31;   \
    const int wy = warp >> 1, wx = warp & 1;                      \
    const int g = lane >> 2, t = lane & 3;                        \
    float acc[2][4][4];                                           \
    _Pragma("unroll")                                             \
    for (int i = 0; i < 2; i++)                                   \
        _Pragma("unroll")                                         \
        for (int j = 0; j < 4; j++)                               \
            _Pragma("unroll")                                     \
            for (int q = 0; q < 4; q++) acc[i][j][q] = 0.f;

// patch embed GEMM (with bias): grid (8, 8).
__global__ void __launch_bounds__(256)
gemm32_plain(const float* __restrict__ A, int lda,
             const float* __restrict__ W, int ldw,
             float* __restrict__ C, int ldc, int K,
             const float* __restrict__ bias)
{
    const int rowBase = blockIdx.y * 128;
    const int colBase = blockIdx.x * 64;
    MMA_PROLOGUE
    mma_core_db(A + (size_t)rowBase * lda, lda, W + (size_t)colBase * ldw, ldw, K, acc);

#pragma unroll
    for (int mf = 0; mf < 2; mf++) {
        const int r0 = rowBase + wy * 32 + mf * 16 + g;
#pragma unroll
        for (int nt = 0; nt < 4; nt++) {
            int cb = colBase + wx * 32 + nt * 8 + 2 * t;
            float v0 = acc[mf][nt][0], v1 = acc[mf][nt][1];
            float v2 = acc[mf][nt][2], v3 = acc[mf][nt][3];
            if (bias) { v0 += bias[cb]; v1 += bias[cb + 1]; v2 += bias[cb]; v3 += bias[cb + 1]; }
            *reinterpret_cast<float2*>(&C[(size_t)r0 * ldc + cb])       = make_float2(v0, v1);
            *reinterpret_cast<float2*>(&C[(size_t)(r0 + 8) * ldc + cb]) = make_float2(v2, v3);
        }
    }
}

// x_proj partial, split-K(8) + dir-batched: grid (8 kc, 8 m, 2 dir). N=64.
__global__ void __launch_bounds__(256)
gemm32_xproj_part(const float* __restrict__ ubase,
                  const float* __restrict__ W0, const float* __restrict__ W1,
                  float* __restrict__ partial)
{
    const int kc  = blockIdx.x;
    const int dir = blockIdx.z;
    const float* A = ubase + (size_t)dir * (1024 * 1024) + kc * 128;
    const float* W = (dir ? W1 : W0) + kc * 128;
    const int rowBase = blockIdx.y * 128;
    MMA_PROLOGUE
    mma_core_db(A + (size_t)rowBase * 1024, 1024, W, 1024, 128, acc);

    float* out = partial + ((size_t)(dir * 8 + kc)) * (1024 * 64);
#pragma unroll
    for (int mf = 0; mf < 2; mf++) {
        const int r0 = rowBase + wy * 32 + mf * 16 + g;
#pragma unroll
        for (int nt = 0; nt < 4; nt++) {
            int cb = wx * 32 + nt * 8 + 2 * t;
            *reinterpret_cast<float2*>(&out[(size_t)r0 * 64 + cb])       = make_float2(acc[mf][nt][0], acc[mf][nt][1]);
            *reinterpret_cast<float2*>(&out[(size_t)(r0 + 8) * 64 + cb]) = make_float2(acc[mf][nt][2], acc[mf][nt][3]);
        }
    }
}

__global__ void xproj_reduce(const float* __restrict__ partial, float* __restrict__ xdbase)
{
    int idx = blockIdx.x * 256 + threadIdx.x;          // 2*65536
    int dir = idx >> 16;
    int rem = idx & 65535;
    float s = 0.f;
#pragma unroll
    for (int kc = 0; kc < 8; kc++)
        s += partial[((size_t)(dir * 8 + kc) << 16) + rem];
    xdbase[((size_t)dir << 16) + rem] = s;
}

// ---------------------------------------------------------------------------
// im2col for patch embed
// ---------------------------------------------------------------------------
__global__ void im2col_kernel(const float* __restrict__ x, float* __restrict__ out)
{
    int idx = blockIdx.x * 256 + threadIdx.x;          // 1024*256
    int k = idx & 255;  int m = idx >> 8;
    int q = k & 15;     int p = k >> 4;
    int w = m & 31;     int hh = (m >> 5) & 7;  int b = m >> 8;
    out[idx] = x[((size_t)(b * 128 + hh * 16 + p) << 9) + w * 16 + q];
}

// ---------------------------------------------------------------------------
// LayerNorm (plain, for tiny feat rows).
// ---------------------------------------------------------------------------
__global__ void ln_kernel(const float* __restrict__ x, float* __restrict__ y,
                          const float* __restrict__ w, const float* __restrict__ bsh,
                          int rows)
{
    int warp = (blockIdx.x * blockDim.x + threadIdx.x) >> 5;
    int lane = threadIdx.x & 31;
    if (warp >= rows) return;
    const float* xr = x + (size_t)warp * 512;
    float v[16]; float s = 0.f, s2 = 0.f;
#pragma unroll
    for (int i = 0; i < 16; i++) {
        float tv = xr[lane + i * 32];
        v[i] = tv; s += tv; s2 += tv * tv;
    }
#pragma unroll
    for (int o = 16; o; o >>= 1) {
        s  += __shfl_xor_sync(0xffffffffu, s, o);
        s2 += __shfl_xor_sync(0xffffffffu, s2, o);
    }
    float m   = s * (1.f / 512.f);
    float var = s2 * (1.f / 512.f) - m * m;
    float inv = rsqrtf(var + 1e-5f);
    float* yr = y + (size_t)warp * 512;
#pragma unroll
    for (int i = 0; i < 16; i++) {
        int c = lane + i * 32;
        yr[c] = (v[i] - m) * inv * w[c] + bsh[c];
    }
}

// ---------------------------------------------------------------------------
// Depthwise causal conv (K=4) + SiLU; dir=1 operates on time-flipped sequence.
// ---------------------------------------------------------------------------
__global__ void conv_silu_kernel(const float* __restrict__ xz,
                                 const float* __restrict__ cwf, const float* __restrict__ cbf,
                                 const float* __restrict__ cwb, const float* __restrict__ cbb,
                                 float* __restrict__ u0, float* __restrict__ u1)
{
    int idx = blockIdx.x * 256 + threadIdx.x;          // 0 .. 1M-1
    int dir = blockIdx.y;
    int d = idx & 1023;
    int r = idx >> 10;
    int l = r & 255;  int b = r >> 8;
    const float* cw = dir ? cwb : cwf;
    const float* cb = dir ? cbb : cbf;
    float acc = cb[d];
#pragma unroll
    for (int k = 0; k < 4; k++) {
        int p = l - 3 + k;
        if (p >= 0) {
            int torig = dir ? (255 - p) : p;
            acc += xz[((size_t)(b * 256 + torig) << 11) + d] * cw[d * 4 + k];
        }
    }
    float sg = 1.f / (1.f + __expf(-acc));
    (dir ? u1 : u0)[idx] = acc * sg;
}

// ---------------------------------------------------------------------------
// Selective scan with FUSED dt_proj+softplus. Split-state: 2 threads per
// channel x 8 states. grid (16, 4, 2), 128 threads.
// ---------------------------------------------------------------------------
__global__ void scan_kernel(const float* __restrict__ ubase,
                            const float* __restrict__ xdbase,
                            const float* __restrict__ dtw0, const float* __restrict__ dtw1,
                            const float* __restrict__ dtb0, const float* __restrict__ dtb1,
                            const float* __restrict__ Af,  const float* __restrict__ Ab,
                            const float* __restrict__ Dfp, const float* __restrict__ Dbp,
                            float* __restrict__ ybase)
{
    const int tid  = threadIdx.x;
    const int half = tid & 1;
    const int d    = blockIdx.x * 64 + (tid >> 1);
    const int b    = blockIdx.y;
    const int dir  = blockIdx.z;
    const float* u  = ubase  + (size_t)dir * (1024 * 1024);
    const float* xd = xdbase + (size_t)dir * (1024 * XDW);
    const float* dtw = (dir ? dtw1 : dtw0) + d * 32 + half * 16;
    const float  dtb = (dir ? dtb1 : dtb0)[d];
    const float* Al = dir ? Ab  : Af;
    const float* Dp = dir ? Dbp : Dfp;
    float* y = ybase + (size_t)dir * (1024 * 1024);

    float w[16];
#pragma unroll
    for (int i = 0; i < 16; i++) w[i] = dtw[i];
    float A[8];
#pragma unroll
    for (int s = 0; s < 8; s++) A[s] = -__expf(Al[d * NS + half * 8 + s]);
    float Dv = Dp[d];
    float st[8];
#pragma unroll
    for (int s = 0; s < 8; s++) st[s] = 0.f;

    __shared__ float sXD[256];
    const size_t rowbase = (size_t)b * 256;
    for (int t0 = 0; t0 < 256; t0 += 4) {
        sXD[tid]       = xd[(rowbase + t0 + (tid >> 6)) * XDW + (tid & 63)];
        sXD[tid + 128] = xd[(rowbase + t0 + 2 + (tid >> 6)) * XDW + (tid & 63)];
        __syncthreads();
        float uv[4];
#pragma unroll
        for (int q = 0; q < 4; q++)
            uv[q] = u[(rowbase + t0 + q) * 1024 + d];
#pragma unroll
        for (int q = 0; q < 4; q++) {
            const float* xr = sXD + q * 64;
            float dot = 0.f;
#pragma unroll
            for (int i = 0; i < 16; i++) dot = fmaf(w[i], xr[half * 16 + i], dot);
            dot += __shfl_xor_sync(0xffffffffu, dot, 1);
            float dtv = dot + dtb;
            dtv = (dtv > 20.f) ? dtv : log1pf(__expf(dtv));

            const float* bc = xr + 32 + half * 8;
            float du = dtv * uv[q];
            float yv = 0.f;
#pragma unroll
            for (int s = 0; s < 8; s++) {
                float dA = __expf(dtv * A[s]);
                st[s] = st[s] * dA + du * bc[s];
                yv   += st[s] * bc[16 + s];
            }
            yv += __shfl_xor_sync(0xffffffffu, yv, 1);
            if (half == 0)
                y[(rowbase + t0 + q) * 1024 + d] = yv + uv[q] * Dv;
        }
        __syncthreads();
    }
}

// ---------------------------------------------------------------------------
// Head: fused LN-apply + mean pool. feat[b][d] = mean_l ln(h[b,l])[d].
// grid 8 x 256.
// ---------------------------------------------------------------------------
__global__ void pool_ln_kernel(const float* __restrict__ h,
                               const float* __restrict__ stats,
                               const float* __restrict__ w, const float* __restrict__ bsh,
                               float* __restrict__ feat)
{
    int idx = blockIdx.x * 256 + threadIdx.x;          // 4*512
    if (idx >= 4 * 512) return;
    int b = idx >> 9, d = idx & 511;
    float s = 0.f;
    for (int l = 0; l < 256; l++) {
        int r = b * 256 + l;
        float v = (h[((size_t)r << 9) + d] - stats[r * 2]) * stats[r * 2 + 1];
        s += v;
    }
    feat[idx] = (s * (1.f / 256.f)) * w[d] + bsh[d];
}

// ---------------------------------------------------------------------------
// Small FC: one warp per output element.
// ---------------------------------------------------------------------------
__global__ void fc_kernel(const float* __restrict__ in, const float* __restrict__ Wt,
                          const float* __restrict__ bias, float* __restrict__ out,
                          int Brows, int N, int K, int relu)
{
    int warp = (blockIdx.x * blockDim.x + threadIdx.x) >> 5;
    int lane = threadIdx.x & 31;
    if (warp >= Brows * N) return;
    int b = warp / N, j = warp % N;
    const float* ir = in + (size_t)b * K;
    const float* wr = Wt + (size_t)j * K;
    float s = 0.f;
    for (int k = lane; k < K; k += 32) s += ir[k] * wr[k];
#pragma unroll
    for (int o = 16; o; o >>= 1) s += __shfl_xor_sync(0xffffffffu, s, o);
    if (lane == 0) {
        float v = s + bias[j];
        if (relu) v = fmaxf(v, 0.f);
        out[warp] = v;
    }
}

// ---------------------------------------------------------------------------
// kernel_launch
// ---------------------------------------------------------------------------
extern "C" void kernel_launch(void* const* d_in, const int* in_sizes, int n_in,
                              void* d_out, int out_size)
{
    float* sc = nullptr;
    cudaGetSymbolAddress((void**)&sc, g_scratch);

    auto F = [&](int i) { return (const float*)d_in[i]; };
    const float *x = F(0), *patch_w = F(1), *patch_b = F(2), *in_proj_w = F(3);
    const float *conv_w_f, *conv_b_f, *conv_w_b, *conv_b_b;
    const float *xproj_w_f, *xproj_w_b, *dtproj_w_f, *dtproj_b_f, *dtproj_w_b, *dtproj_b_b;
    const float *A_log_f, *A_log_b, *D_f, *D_b;

    if (in_sizes[6] == 16384) {
        conv_w_f = F(4);  conv_b_f = F(5);  conv_w_b = F(6);  conv_b_b = F(7);
        xproj_w_f = F(8); xproj_w_b = F(9);
        dtproj_w_f = F(10); dtproj_b_f = F(11); dtproj_w_b = F(12); dtproj_b_b = F(13);
        A_log_f = F(14); A_log_b = F(15); D_f = F(16); D_b = F(17);
    } else {
        conv_w_f = F(4);  conv_b_f = F(5);  xproj_w_f = F(6); dtproj_w_f = F(7);
        dtproj_b_f = F(8); A_log_f = F(9);  D_f = F(10);
        conv_w_b = F(11); conv_b_b = F(12); xproj_w_b = F(13); dtproj_w_b = F(14);
        dtproj_b_b = F(15); A_log_b = F(16); D_b = F(17);
    }
    const float *out_proj_w = F(18), *norm_w = F(19), *norm_b = F(20);
    const float *normf_w = F(21), *normf_b = F(22), *ln_w = F(23), *ln_b = F(24);
    const float *fc1_w = F(25), *fc1_b = F(26), *fc2_w = F(27), *fc2_b = F(28);

    float* h_p    = sc + OFF_H;
    float* xz_p   = sc + OFF_XZ;
    float* u_p    = sc + OFF_U0;
    float* xd_p   = sc + OFF_XD0;
    float* y_p    = sc + OFF_Y0;
    float* im_p   = sc + OFF_IM;
    float* xpp_p  = sc + OFF_XPP;
    float* opp_p  = sc + OFF_OPP;
    float* st_p   = sc + OFF_ST;
    float* feat_p = sc + OFF_FEAT;
    float* c_p    = sc + OFF_C;
    float* f1_p   = sc + OFF_F1;

    // ---- patch embed --------------------------------------------------------
    im2col_kernel<<<1024, 256>>>(x, im_p);
    gemm32_plain<<<dim3(8, 8), 256>>>(im_p, 256, patch_w, 256, h_p, 512, 256, patch_b);
    stats_kernel<<<128, 256>>>(h_p, st_p);

    for (int i = 0; i < 4; i++) {
        // in_proj with fused LN: 1024 x 2048 x 512 (grid 16x8)
        gemm32_inproj<<<dim3(16, 8), 256>>>(
            h_p, st_p, norm_w + i * 512, norm_b + i * 512,
            in_proj_w + (size_t)i * 2048 * 512, xz_p);

        conv_silu_kernel<<<dim3(4096, 2), 256>>>(
            xz_p,
            conv_w_f + i * 4096, conv_b_f + i * 1024,
            conv_w_b + i * 4096, conv_b_b + i * 1024,
            u_p, u_p + 1024 * 1024);

        gemm32_xproj_part<<<dim3(8, 8, 2), 256>>>(
            u_p, xproj_w_f + (size_t)i * XDW * 1024, xproj_w_b + (size_t)i * XDW * 1024,
            xpp_p);
        xproj_reduce<<<512, 256>>>(xpp_p, xd_p);

        scan_kernel<<<dim3(16, 4, 2), 128>>>(
            u_p, xd_p,
            dtproj_w_f + (size_t)i * 1024 * 32, dtproj_w_b + (size_t)i * 1024 * 32,
            dtproj_b_f + i * 1024, dtproj_b_b + i * 1024,
            A_log_f + i * 16384, A_log_b + i * 16384,
            D_f + i * 1024, D_b + i * 1024,
            y_p);

        // out_proj with fused gate: split-K(4), grid (4,8,4)
        gemm32_op_gate<<<dim3(4, 8, 4), 256>>>(
            y_p, xz_p, out_proj_w + (size_t)i * 512 * 1024, opp_p);
        op_combine_stats<<<128, 256>>>(opp_p, h_p, st_p);
    }

    // ---- head ---------------------------------------------------------------
    pool_ln_kernel<<<8, 256>>>(h_p, st_p, normf_w, normf_b, feat_p);
    ln_kernel<<<1, 256>>>(feat_p, c_p, ln_w, ln_b, 4);
    fc_kernel<<<256, 256>>>(c_p, fc1_w, fc1_b, f1_p, 4, 512, 512, 1);
    fc_kernel<<<5, 256>>>(f1_p, fc2_w, fc2_b, (float*)d_out, 4, 10, 512, 0);
}